// round 5
// baseline (speedup 1.0000x reference)
#include <cuda_runtime.h>
#include <cstdint>

// y[b, i, c] = x[b, i+1, c] - x[b, i, c]
// x: [B=64, L=16384, C=32] fp32, y: [B, L-1, C] fp32
// v8 = 8 fp32 = 32 B (Blackwell 256-bit ld/st). Row = 128 B = 4 v8; shift = +4 v8.
// Each thread owns 8 CONSECUTIVE v8 chunks -> out[k] = x[c0+k+4] - x[c0+k],
// so 12 loads cover all 8 outputs (register reuse of the overlapping 4).

static constexpr int B = 64;
static constexpr int L = 16384;
static constexpr int C = 32;
static constexpr int IN_V8_PER_B  = L * C / 8;        // 65536
static constexpr int OUT_V8_PER_B = (L - 1) * C / 8;  // 65532
static constexpr int VPT = 8;                         // consecutive v8 chunks per thread
static constexpr int NLD = VPT + 4;                   // 12 loads per thread
static constexpr int TPB = 256;
static constexpr int V8_PER_BLOCK = VPT * TPB;        // 2048

struct V8 { float v[8]; };

__device__ __forceinline__ void ldg_v8(const float* p, V8& r) {
    asm volatile(
        "ld.global.v8.b32 {%0,%1,%2,%3,%4,%5,%6,%7}, [%8];"
        : "=f"(r.v[0]), "=f"(r.v[1]), "=f"(r.v[2]), "=f"(r.v[3]),
          "=f"(r.v[4]), "=f"(r.v[5]), "=f"(r.v[6]), "=f"(r.v[7])
        : "l"(p));
}

__device__ __forceinline__ void stg_v8(float* p, const V8& r) {
    asm volatile(
        "st.global.v8.b32 [%0], {%1,%2,%3,%4,%5,%6,%7,%8};"
        :: "l"(p),
           "f"(r.v[0]), "f"(r.v[1]), "f"(r.v[2]), "f"(r.v[3]),
           "f"(r.v[4]), "f"(r.v[5]), "f"(r.v[6]), "f"(r.v[7])
        : "memory");
}

__global__ void __launch_bounds__(TPB, 2) diff1d_kernel(
    const float* __restrict__ x, float* __restrict__ y)
{
    const int b = blockIdx.y;
    const float* __restrict__ xin = x + (size_t)b * (IN_V8_PER_B * 8);
    float* __restrict__ yout = y + (size_t)b * (OUT_V8_PER_B * 8);

    // First v8 chunk owned by this thread (consecutive ownership).
    const int c0 = blockIdx.x * V8_PER_BLOCK + threadIdx.x * VPT;

    if (blockIdx.x != gridDim.x - 1) {
        // Full block: 12 front-batched loads, 8 outputs via register reuse.
        V8 ld[NLD];
#pragma unroll
        for (int k = 0; k < NLD; k++)
            ldg_v8(xin + (size_t)(c0 + k) * 8, ld[k]);

#pragma unroll
        for (int k = 0; k < VPT; k++) {
            V8 r;
#pragma unroll
            for (int j = 0; j < 8; j++) r.v[j] = ld[k + 4].v[j] - ld[k].v[j];
            stg_v8(yout + (size_t)(c0 + k) * 8, r);
        }
    } else {
        // Tail block: guarded per chunk (only last 4 v8s of the batch are OOB).
#pragma unroll
        for (int k = 0; k < VPT; k++) {
            const int i = c0 + k;
            if (i < OUT_V8_PER_B) {
                V8 a, bb, r;
                ldg_v8(xin + (size_t)i * 8, a);
                ldg_v8(xin + (size_t)(i + 4) * 8, bb);
#pragma unroll
                for (int j = 0; j < 8; j++) r.v[j] = bb.v[j] - a.v[j];
                stg_v8(yout + (size_t)i * 8, r);
            }
        }
    }
}

extern "C" void kernel_launch(void* const* d_in, const int* in_sizes, int n_in,
                              void* d_out, int out_size)
{
    (void)in_sizes; (void)n_in; (void)out_size;
    const float* x = (const float*)d_in[0];
    float* y = (float*)d_out;

    dim3 block(TPB);
    dim3 grid((OUT_V8_PER_B + V8_PER_BLOCK - 1) / V8_PER_BLOCK, B);  // (32, 64)
    diff1d_kernel<<<grid, block>>>(x, y);
}

// round 7
// speedup vs baseline: 1.3297x; 1.3297x over previous
#include <cuda_runtime.h>
#include <cstdint>

// y[b, i, c] = x[b, i+1, c] - x[b, i, c]
// x: [B=64, L=16384, C=32] fp32, y: [B, L-1, C] fp32
// v8 = 8 fp32 = 32 B (Blackwell 256-bit ld/st). Row = 128 B = 4 v8; shift = +4 v8.
// Lane-contiguous layout (i = base + tid + k*TPB, in v8 units) — mandatory for
// coalescing (R4 post-mortem). L2::evict_first on loads: input lines are dead
// after their two temporally-adjacent uses; keep L2 for output write-combining.

static constexpr int B = 64;
static constexpr int L = 16384;
static constexpr int C = 32;
static constexpr int IN_V8_PER_B  = L * C / 8;        // 65536
static constexpr int OUT_V8_PER_B = (L - 1) * C / 8;  // 65532
static constexpr int VPT = 4;                         // v8 chunks per thread (strided)
static constexpr int TPB = 256;
static constexpr int V8_PER_BLOCK = VPT * TPB;        // 1024

struct V8 { float v[8]; };

__device__ __forceinline__ void ldg_ef_v8(const float* p, V8& r) {
    asm volatile(
        "ld.global.L2::evict_first.v8.b32 {%0,%1,%2,%3,%4,%5,%6,%7}, [%8];"
        : "=f"(r.v[0]), "=f"(r.v[1]), "=f"(r.v[2]), "=f"(r.v[3]),
          "=f"(r.v[4]), "=f"(r.v[5]), "=f"(r.v[6]), "=f"(r.v[7])
        : "l"(p));
}

__device__ __forceinline__ void stg_v8(float* p, const V8& r) {
    asm volatile(
        "st.global.v8.b32 [%0], {%1,%2,%3,%4,%5,%6,%7,%8};"
        :: "l"(p),
           "f"(r.v[0]), "f"(r.v[1]), "f"(r.v[2]), "f"(r.v[3]),
           "f"(r.v[4]), "f"(r.v[5]), "f"(r.v[6]), "f"(r.v[7])
        : "memory");
}

__global__ void __launch_bounds__(TPB) diff1d_kernel(
    const float* __restrict__ x, float* __restrict__ y)
{
    const int b = blockIdx.y;
    const float* __restrict__ xin = x + (size_t)b * (IN_V8_PER_B * 8);
    float* __restrict__ yout = y + (size_t)b * (OUT_V8_PER_B * 8);

    const int base = blockIdx.x * V8_PER_BLOCK + threadIdx.x;  // in v8 units

    if (blockIdx.x != gridDim.x - 1) {
        // Full block: branch-free, all 8 loads front-batched for max MLP.
        V8 a[VPT], bb[VPT];
#pragma unroll
        for (int k = 0; k < VPT; k++) {
            const int i = base + k * TPB;
            ldg_ef_v8(xin + (size_t)i * 8, a[k]);
            ldg_ef_v8(xin + (size_t)(i + 4) * 8, bb[k]);  // +4 v8 = next row along L
        }
#pragma unroll
        for (int k = 0; k < VPT; k++) {
            const int i = base + k * TPB;
            V8 r;
#pragma unroll
            for (int j = 0; j < 8; j++) r.v[j] = bb[k].v[j] - a[k].v[j];
            stg_v8(yout + (size_t)i * 8, r);
        }
    } else {
        // Tail block: guarded per chunk.
#pragma unroll
        for (int k = 0; k < VPT; k++) {
            const int i = base + k * TPB;
            if (i < OUT_V8_PER_B) {
                V8 a, bb, r;
                ldg_ef_v8(xin + (size_t)i * 8, a);
                ldg_ef_v8(xin + (size_t)(i + 4) * 8, bb);
#pragma unroll
                for (int j = 0; j < 8; j++) r.v[j] = bb.v[j] - a.v[j];
                stg_v8(yout + (size_t)i * 8, r);
            }
        }
    }
}

extern "C" void kernel_launch(void* const* d_in, const int* in_sizes, int n_in,
                              void* d_out, int out_size)
{
    (void)in_sizes; (void)n_in; (void)out_size;
    const float* x = (const float*)d_in[0];
    float* y = (float*)d_out;

    dim3 block(TPB);
    dim3 grid((OUT_V8_PER_B + V8_PER_BLOCK - 1) / V8_PER_BLOCK, B);  // (64, 64)
    diff1d_kernel<<<grid, block>>>(x, y);
}

// round 8
// speedup vs baseline: 1.3830x; 1.0401x over previous
#include <cuda_runtime.h>
#include <cstdint>

// y[b, i, c] = x[b, i+1, c] - x[b, i, c]
// x: [B=64, L=16384, C=32] fp32, y: [B, L-1, C] fp32
// v8 = 8 fp32 = 32 B (Blackwell 256-bit ld/st). Row = 128 B = 4 v8; shift = +4 v8.
// Lane-contiguous layout (i = base + tid + k*TPB, in v8 units) — mandatory for
// coalescing (R4 post-mortem). Loads: default policy (R6 post-mortem: evict_first
// on loads regressed). Stores: L2::evict_first — output is never re-read; mark
// dirty lines for early writeback so the drain overlaps execution instead of
// serializing into the inter-replay gap.

static constexpr int B = 64;
static constexpr int L = 16384;
static constexpr int C = 32;
static constexpr int IN_V8_PER_B  = L * C / 8;        // 65536
static constexpr int OUT_V8_PER_B = (L - 1) * C / 8;  // 65532
static constexpr int VPT = 4;                         // v8 chunks per thread (strided)
static constexpr int TPB = 256;
static constexpr int V8_PER_BLOCK = VPT * TPB;        // 1024

struct V8 { float v[8]; };

__device__ __forceinline__ void ldg_v8(const float* p, V8& r) {
    asm volatile(
        "ld.global.v8.b32 {%0,%1,%2,%3,%4,%5,%6,%7}, [%8];"
        : "=f"(r.v[0]), "=f"(r.v[1]), "=f"(r.v[2]), "=f"(r.v[3]),
          "=f"(r.v[4]), "=f"(r.v[5]), "=f"(r.v[6]), "=f"(r.v[7])
        : "l"(p));
}

__device__ __forceinline__ void stg_ef_v8(float* p, const V8& r) {
    asm volatile(
        "st.global.L2::evict_first.v8.b32 [%0], {%1,%2,%3,%4,%5,%6,%7,%8};"
        :: "l"(p),
           "f"(r.v[0]), "f"(r.v[1]), "f"(r.v[2]), "f"(r.v[3]),
           "f"(r.v[4]), "f"(r.v[5]), "f"(r.v[6]), "f"(r.v[7])
        : "memory");
}

__global__ void __launch_bounds__(TPB) diff1d_kernel(
    const float* __restrict__ x, float* __restrict__ y)
{
    const int b = blockIdx.y;
    const float* __restrict__ xin = x + (size_t)b * (IN_V8_PER_B * 8);
    float* __restrict__ yout = y + (size_t)b * (OUT_V8_PER_B * 8);

    const int base = blockIdx.x * V8_PER_BLOCK + threadIdx.x;  // in v8 units

    if (blockIdx.x != gridDim.x - 1) {
        // Full block: branch-free, all 8 loads front-batched for max MLP.
        V8 a[VPT], bb[VPT];
#pragma unroll
        for (int k = 0; k < VPT; k++) {
            const int i = base + k * TPB;
            ldg_v8(xin + (size_t)i * 8, a[k]);
            ldg_v8(xin + (size_t)(i + 4) * 8, bb[k]);  // +4 v8 = next row along L
        }
#pragma unroll
        for (int k = 0; k < VPT; k++) {
            const int i = base + k * TPB;
            V8 r;
#pragma unroll
            for (int j = 0; j < 8; j++) r.v[j] = bb[k].v[j] - a[k].v[j];
            stg_ef_v8(yout + (size_t)i * 8, r);
        }
    } else {
        // Tail block: guarded per chunk.
#pragma unroll
        for (int k = 0; k < VPT; k++) {
            const int i = base + k * TPB;
            if (i < OUT_V8_PER_B) {
                V8 a, bb, r;
                ldg_v8(xin + (size_t)i * 8, a);
                ldg_v8(xin + (size_t)(i + 4) * 8, bb);
#pragma unroll
                for (int j = 0; j < 8; j++) r.v[j] = bb.v[j] - a.v[j];
                stg_ef_v8(yout + (size_t)i * 8, r);
            }
        }
    }
}

extern "C" void kernel_launch(void* const* d_in, const int* in_sizes, int n_in,
                              void* d_out, int out_size)
{
    (void)in_sizes; (void)n_in; (void)out_size;
    const float* x = (const float*)d_in[0];
    float* y = (float*)d_out;

    dim3 block(TPB);
    dim3 grid((OUT_V8_PER_B + V8_PER_BLOCK - 1) / V8_PER_BLOCK, B);  // (64, 64)
    diff1d_kernel<<<grid, block>>>(x, y);
}